// round 2
// baseline (speedup 1.0000x reference)
#include <cuda_runtime.h>
#include <cstdint>
#include <cstddef>

// Problem constants
#define NEMB   1024
#define EDIM   256
#define BATCH  8
#define HWL    4096          // 16*16*16
#define NROWS  (BATCH*HWL)   // 32768
#define TM     128
#define TK     64
#define PITCH  260           // floats per smem row; 260*4=1040 bytes, 16B aligned
#define NBLK   (NROWS/TM)    // 256

// Scratch (static device globals — no allocation)
__device__ float  g_zf[NROWS*EDIM];     // z transposed to (N, D), row-major
__device__ float  g_e2[NEMB];           // codebook row norms^2 (correctly rounded fp32)
__device__ int    g_idx[NROWS];         // argmin indices
__device__ double g_partial[NBLK];      // per-block sum of min distances (deterministic)

// packed fp32x2 FMA: acc = a*b + acc (lanewise)
__device__ __forceinline__ void ffma2(unsigned long long &acc,
                                      unsigned long long a,
                                      unsigned long long b) {
    asm("fma.rn.f32x2 %0, %1, %2, %3;" : "=l"(acc) : "l"(a), "l"(b), "l"(acc));
}

// ---------------------------------------------------------------------------
// Kernel A: transpose z (B, D, HWL) -> zf (B*HWL, D)
// ---------------------------------------------------------------------------
__global__ void vq_transpose(const float* __restrict__ z) {
    __shared__ float tile[32][33];
    int b  = blockIdx.z;
    int d0 = blockIdx.y << 5;
    int s0 = blockIdx.x << 5;
    int tx = threadIdx.x, ty = threadIdx.y;   // 32 x 8
    const float* src = z + ((size_t)b*EDIM + d0)*HWL + s0;
    #pragma unroll
    for (int i = 0; i < 32; i += 8)
        tile[ty+i][tx] = src[(size_t)(ty+i)*HWL + tx];
    __syncthreads();
    float* dst = g_zf + ((size_t)b*HWL + s0)*EDIM + d0;
    #pragma unroll
    for (int i = 0; i < 32; i += 8)
        dst[(size_t)(ty+i)*EDIM + tx] = tile[tx][ty+i];
}

// ---------------------------------------------------------------------------
// Kernel B: codebook row norms (double accumulate -> correctly rounded fp32)
// ---------------------------------------------------------------------------
__global__ void vq_e2(const float* __restrict__ cb) {
    int k = blockIdx.x * blockDim.x + threadIdx.x;
    if (k < NEMB) {
        const float* row = cb + (size_t)k*EDIM;
        double s = 0.0;
        for (int d = 0; d < EDIM; d++) { double v = row[d]; s += v*v; }
        g_e2[k] = (float)s;
    }
}

// ---------------------------------------------------------------------------
// Kernel C: fused GEMM + argmin.  dist = fl32( fl32(z2 + e2[k]) - 2*dot )
// TM=128 rows x TK=64 codes per tile, 256 threads, 8x4 register tile per
// thread, f32x2-packed FMAs along d.
// ---------------------------------------------------------------------------
__global__ __launch_bounds__(256, 1)
void vq_main(const float* __restrict__ cb, float* __restrict__ out_idx, int write_idx) {
    extern __shared__ float sm[];
    float* zt   = sm;                       // TM * PITCH
    float* et   = sm + TM*PITCH;            // TK * PITCH
    float* z2s  = et + TK*PITCH;            // TM
    float* e2s  = z2s + TM;                 // TK
    float* redv = e2s + TK;                 // TM

    const int t  = threadIdx.x;
    const int n0 = blockIdx.x * TM;

    // load z tile (coalesced float4 rows)
    {
        const float4* src = (const float4*)(g_zf + (size_t)n0*EDIM);
        for (int i = t; i < TM*(EDIM/4); i += 256) {
            int r = i >> 6, c4 = i & 63;
            float4 v = src[(size_t)r*(EDIM/4) + c4];
            *(float4*)(zt + r*PITCH + (c4 << 2)) = v;
        }
    }
    __syncthreads();

    // z2 per row (fp32; summation order is argmin-invariant — see analysis)
    {
        int r = t >> 1, h = t & 1;
        const float* row = zt + r*PITCH + h*128;
        float s = 0.f;
        #pragma unroll 8
        for (int d = 0; d < 128; d++) s += row[d]*row[d];
        float o = __shfl_xor_sync(0xffffffffu, s, 1);
        if (!h) z2s[r] = s + o;
    }

    const int ty = t >> 4, tx = t & 15;
    float bestv[8]; int besti[8];
    #pragma unroll
    for (int i = 0; i < 8; i++) { bestv[i] = 3.402823466e38f; besti[i] = 0; }

    const float* ztb = zt + ty*8*PITCH;

    for (int k0 = 0; k0 < NEMB; k0 += TK) {
        __syncthreads();   // protect et from previous iteration's readers
        {
            const float4* src = (const float4*)(cb + (size_t)k0*EDIM);
            for (int i = t; i < TK*(EDIM/4); i += 256) {
                int r = i >> 6, c4 = i & 63;
                float4 v = src[(size_t)r*(EDIM/4) + c4];
                *(float4*)(et + r*PITCH + (c4 << 2)) = v;
            }
            if (t < TK) e2s[t] = g_e2[k0 + t];
        }
        __syncthreads();

        unsigned long long acc[8][4];
        #pragma unroll
        for (int i = 0; i < 8; i++)
            #pragma unroll
            for (int j = 0; j < 4; j++) acc[i][j] = 0ull;

        const float* etb = et + tx*4*PITCH;
        #pragma unroll 4
        for (int d4 = 0; d4 < EDIM/4; d4++) {
            ulonglong2 a[8], bb[4];
            #pragma unroll
            for (int i = 0; i < 8; i++)
                a[i] = *(const ulonglong2*)(ztb + i*PITCH + (d4 << 2));
            #pragma unroll
            for (int j = 0; j < 4; j++)
                bb[j] = *(const ulonglong2*)(etb + j*PITCH + (d4 << 2));
            #pragma unroll
            for (int i = 0; i < 8; i++)
                #pragma unroll
                for (int j = 0; j < 4; j++) {
                    ffma2(acc[i][j], a[i].x, bb[j].x);
                    ffma2(acc[i][j], a[i].y, bb[j].y);
                }
        }

        #pragma unroll
        for (int i = 0; i < 8; i++) {
            float z2r = z2s[ty*8 + i];
            #pragma unroll
            for (int j = 0; j < 4; j++) {
                union { unsigned long long u; float2 f; } c; c.u = acc[i][j];
                float dot  = c.f.x + c.f.y;
                float r1   = z2r + e2s[tx*4 + j];     // fl32(z2 + e2)
                float dist = r1 - 2.0f*dot;           // fl32(r1 - 2*dot), 2*dot exact
                int   kk   = k0 + tx*4 + j;
                if (dist < bestv[i]) { bestv[i] = dist; besti[i] = kk; } // first-min
            }
        }
    }

    // reduce (val, idx) across the 16 tx lanes (half-warp), first-min ties
    #pragma unroll
    for (int i = 0; i < 8; i++) {
        float v = bestv[i]; int ix = besti[i];
        #pragma unroll
        for (int off = 8; off > 0; off >>= 1) {
            float ov = __shfl_down_sync(0xffffffffu, v,  off, 16);
            int   oi = __shfl_down_sync(0xffffffffu, ix, off, 16);
            if (ov < v || (ov == v && oi < ix)) { v = ov; ix = oi; }
        }
        if (tx == 0) {
            int n = n0 + ty*8 + i;
            g_idx[n] = ix;
            if (write_idx) out_idx[n] = (float)ix;
            redv[ty*8 + i] = v;
        }
    }
    __syncthreads();
    if (t == 0) {
        double s = 0.0;
        for (int r = 0; r < TM; r++) s += (double)redv[r];
        g_partial[blockIdx.x] = s;   // deterministic (no atomics)
    }
}

// ---------------------------------------------------------------------------
// Kernel D: gather codebook rows by index and write (B, D, HWL) layout
// ---------------------------------------------------------------------------
__global__ __launch_bounds__(256)
void vq_scatter(const float* __restrict__ cb, float* __restrict__ outq) {
    __shared__ float qt[32*257];
    int b  = blockIdx.y;
    int s0 = blockIdx.x << 5;
    int t  = threadIdx.x;
    for (int i = t; i < 32*64; i += 256) {
        int r = i >> 6, c4 = i & 63;
        int k = g_idx[b*HWL + s0 + r];
        float4 v = *(const float4*)(cb + (size_t)k*EDIM + (c4 << 2));
        float* dst = qt + r*257 + (c4 << 2);
        dst[0] = v.x; dst[1] = v.y; dst[2] = v.z; dst[3] = v.w;
    }
    __syncthreads();
    int s = t & 31, dh = t >> 5;
    #pragma unroll
    for (int d = dh; d < EDIM; d += 8)
        outq[((size_t)b*EDIM + d)*HWL + s0 + s] = qt[s*257 + d];
}

// ---------------------------------------------------------------------------
// Kernel E: finalize loss = 1.25 * sum(min_dist) / (N*D)
// ---------------------------------------------------------------------------
__global__ void vq_finalize(float* out_loss) {
    double s = 0.0;
    for (int i = 0; i < NBLK; i++) s += g_partial[i];
    *out_loss = (float)(1.25 * s / (double)((size_t)NROWS*EDIM));
}

// ---------------------------------------------------------------------------
extern "C" void kernel_launch(void* const* d_in, const int* in_sizes, int n_in,
                              void* d_out, int out_size) {
    const float* z  = (const float*)d_in[0];
    const float* cb = (const float*)d_in[1];
    if (n_in >= 2 && in_sizes[0] == NEMB*EDIM && in_sizes[1] == NROWS*EDIM) {
        const float* tmp = z; z = cb; cb = tmp;   // defensive input-order check
    }
    float* out = (float*)d_out;

    const int QN = NROWS*EDIM;                    // 8388608
    bool has_quant = (out_size >= QN);
    bool full      = (out_size == QN + NROWS + 1);
    float* out_idx  = full ? out + QN         : nullptr;
    float* out_loss = full ? out + QN + NROWS : nullptr;

    const int smem_c = (TM*PITCH + TK*PITCH + TM + TK + TM) * 4;  // ~201 KB
    cudaFuncSetAttribute(vq_main, cudaFuncAttributeMaxDynamicSharedMemorySize, smem_c);

    vq_transpose<<<dim3(HWL/32, EDIM/32, BATCH), dim3(32, 8)>>>(z);
    vq_e2<<<(NEMB + 255)/256, 256>>>(cb);
    vq_main<<<NBLK, 256, smem_c>>>(cb, out_idx, full ? 1 : 0);
    if (has_quant)
        vq_scatter<<<dim3(HWL/32, BATCH), 256>>>(cb, out);
    if (full)
        vq_finalize<<<1, 1>>>(out_loss);
}

// round 3
// speedup vs baseline: 1.5175x; 1.5175x over previous
#include <cuda_runtime.h>
#include <cstdint>
#include <cstddef>

// Problem constants
#define NEMB   1024
#define EDIM   256
#define BATCH  8
#define HWL    4096          // 16*16*16
#define NROWS  (BATCH*HWL)   // 32768
#define TM     128
#define TKC    64            // codes per k-tile
#define PITCH  284           // words per smem row (256 data + up to 28 skew)
#define NBLK   (NROWS/TM)    // 256

// Scratch (static device globals — no allocation)
__device__ float  g_zf[NROWS*EDIM];     // z transposed to (N, D), row-major
__device__ float  g_e2[NEMB];           // codebook row norms^2
__device__ int    g_idx[NROWS];         // argmin indices
__device__ double g_partial[NBLK];      // per-block sum of min distances

// packed fp32x2 FMA: acc = a*b + acc (lanewise)
__device__ __forceinline__ void ffma2(unsigned long long &acc,
                                      unsigned long long a,
                                      unsigned long long b) {
    asm("fma.rn.f32x2 %0, %1, %2, %3;" : "=l"(acc) : "l"(a), "l"(b), "l"(acc));
}

// Skewed smem offsets (conflict-free LDS.128 groups, 16B-aligned)
__device__ __forceinline__ int zoff(int r) { return r*PITCH + (((r>>3)&7)<<2); }
__device__ __forceinline__ int eoff(int c) { return c*PITCH + (((c>>2)&7)<<2); }

// ---------------------------------------------------------------------------
// Kernel A: transpose z (B, D, HWL) -> zf (B*HWL, D)
// ---------------------------------------------------------------------------
__global__ void vq_transpose(const float* __restrict__ z) {
    __shared__ float tile[32][33];
    int b  = blockIdx.z;
    int d0 = blockIdx.y << 5;
    int s0 = blockIdx.x << 5;
    int tx = threadIdx.x, ty = threadIdx.y;   // 32 x 8
    const float* src = z + ((size_t)b*EDIM + d0)*HWL + s0;
    #pragma unroll
    for (int i = 0; i < 32; i += 8)
        tile[ty+i][tx] = src[(size_t)(ty+i)*HWL + tx];
    __syncthreads();
    float* dst = g_zf + ((size_t)b*HWL + s0)*EDIM + d0;
    #pragma unroll
    for (int i = 0; i < 32; i += 8)
        dst[(size_t)(ty+i)*EDIM + tx] = tile[tx][ty+i];
}

// ---------------------------------------------------------------------------
// Kernel B: codebook row norms (double accumulate -> correctly rounded fp32)
// ---------------------------------------------------------------------------
__global__ void vq_e2(const float* __restrict__ cb) {
    int k = blockIdx.x * blockDim.x + threadIdx.x;
    if (k < NEMB) {
        const float* row = cb + (size_t)k*EDIM;
        double s = 0.0;
        for (int d = 0; d < EDIM; d++) { double v = row[d]; s += v*v; }
        g_e2[k] = (float)s;
    }
}

// ---------------------------------------------------------------------------
// Kernel C: fused GEMM + argmin.  dist = fl32( fl32(z2 + e2[k]) - 2*dot )
// Block tile 128 rows x 64 codes. 8 warps as 4 row-warps x 2 col-warps;
// warp tile 32x32; lane layout 4 row-groups x 8 code-groups; thread tile
// 8 rows x 4 codes, d-paired f32x2 accumulators.
// ---------------------------------------------------------------------------
__global__ __launch_bounds__(256, 1)
void vq_main(const float* __restrict__ cb, float* __restrict__ out_idx, int write_idx) {
    extern __shared__ float sm[];
    float* zt   = sm;                        // TM * PITCH
    float* et   = zt + TM*PITCH;             // TKC * PITCH
    float* z2s  = et + TKC*PITCH;            // TM
    float* e2s  = z2s + TM;                  // TKC
    float* vA   = e2s + TKC;                 // TM  (cw=0 best val)
    float* vB   = vA + TM;                   // TM  (cw=1 best val)
    int*   iA   = (int*)(vB + TM);           // TM
    int*   iB   = iA + TM;                   // TM

    const int t  = threadIdx.x;
    const int n0 = blockIdx.x * TM;

    // load z tile (coalesced float4 rows into skewed layout)
    {
        const float4* src = (const float4*)(g_zf + (size_t)n0*EDIM);
        for (int i = t; i < TM*(EDIM/4); i += 256) {
            int r = i >> 6, c4 = i & 63;
            float4 v = src[(size_t)r*(EDIM/4) + c4];
            *(float4*)(zt + zoff(r) + (c4 << 2)) = v;
        }
    }
    __syncthreads();

    // z2 per row (fp32; summation order is argmin-invariant)
    {
        int r = t >> 1, h = t & 1;
        const float* row = zt + zoff(r) + h*128;
        float s = 0.f;
        #pragma unroll 8
        for (int d = 0; d < 128; d++) s += row[d]*row[d];
        float o = __shfl_xor_sync(0xffffffffu, s, 1);
        if (!h) z2s[r] = s + o;
    }

    // thread decomposition
    const int w    = t >> 5;
    const int lane = t & 31;
    const int rw   = w >> 1;            // 0..3 row warp
    const int cw   = w & 1;             // 0..1 col warp
    const int rg   = lane >> 3;         // 0..3 row group
    const int cg   = lane & 7;          // 0..7 code group
    const int rowbase = rw*32 + rg*8;   // 8 rows
    const int colbase = cw*32 + cg*4;   // 4 codes (within tile)

    float bestv[8]; int besti[8];
    #pragma unroll
    for (int i = 0; i < 8; i++) { bestv[i] = 3.402823466e38f; besti[i] = 0; }

    const float* ap = zt + zoff(rowbase);

    for (int k0 = 0; k0 < NEMB; k0 += TKC) {
        __syncthreads();   // protect et from previous iteration's readers
        {
            const float4* src = (const float4*)(cb + (size_t)k0*EDIM);
            for (int i = t; i < TKC*(EDIM/4); i += 256) {
                int r = i >> 6, c4 = i & 63;
                float4 v = src[(size_t)r*(EDIM/4) + c4];
                *(float4*)(et + eoff(r) + (c4 << 2)) = v;
            }
            if (t < TKC) e2s[t] = g_e2[k0 + t];
        }
        __syncthreads();

        unsigned long long acc[8][4];
        #pragma unroll
        for (int i = 0; i < 8; i++)
            #pragma unroll
            for (int j = 0; j < 4; j++) acc[i][j] = 0ull;

        const float* bp = et + eoff(colbase);

        #pragma unroll 2
        for (int d4 = 0; d4 < EDIM/4; d4++) {
            ulonglong2 a[8], bb[4];
            #pragma unroll
            for (int i = 0; i < 8; i++)
                a[i] = *(const ulonglong2*)(ap + i*PITCH + (d4 << 2));
            #pragma unroll
            for (int j = 0; j < 4; j++)
                bb[j] = *(const ulonglong2*)(bp + j*PITCH + (d4 << 2));
            #pragma unroll
            for (int i = 0; i < 8; i++)
                #pragma unroll
                for (int j = 0; j < 4; j++)
                    ffma2(acc[i][j], a[i].x, bb[j].x);
            #pragma unroll
            for (int i = 0; i < 8; i++)
                #pragma unroll
                for (int j = 0; j < 4; j++)
                    ffma2(acc[i][j], a[i].y, bb[j].y);
        }

        #pragma unroll
        for (int i = 0; i < 8; i++) {
            float z2r = z2s[rowbase + i];
            #pragma unroll
            for (int j = 0; j < 4; j++) {
                union { unsigned long long u; float2 f; } c; c.u = acc[i][j];
                float dot  = c.f.x + c.f.y;
                float r1   = z2r + e2s[colbase + j];   // fl32(z2 + e2)
                float dist = r1 - 2.0f*dot;            // fl32(r1 - 2*dot)
                int   kk   = k0 + colbase + j;
                if (dist < bestv[i]) { bestv[i] = dist; besti[i] = kk; } // first-min
            }
        }
    }

    // reduce across the 8 cg lanes (width-8 segments), first-min ties
    #pragma unroll
    for (int i = 0; i < 8; i++) {
        float v = bestv[i]; int ix = besti[i];
        #pragma unroll
        for (int off = 4; off > 0; off >>= 1) {
            float ov = __shfl_down_sync(0xffffffffu, v,  off, 8);
            int   oi = __shfl_down_sync(0xffffffffu, ix, off, 8);
            if (ov < v || (ov == v && oi < ix)) { v = ov; ix = oi; }
        }
        if (cg == 0) {
            int rr = rowbase + i;
            if (cw == 0) { vA[rr] = v; iA[rr] = ix; }
            else         { vB[rr] = v; iB[rr] = ix; }
        }
    }
    __syncthreads();

    // combine the two col-warps per row; write outputs
    if (t < TM) {
        float v0 = vA[t]; int i0 = iA[t];
        float v1 = vB[t]; int i1 = iB[t];
        if (v1 < v0 || (v1 == v0 && i1 < i0)) { v0 = v1; i0 = i1; }
        int n = n0 + t;
        g_idx[n] = i0;
        if (write_idx) out_idx[n] = (float)i0;
        vA[t] = v0;   // reuse as per-row min for loss
    }
    __syncthreads();
    if (t == 0) {
        double s = 0.0;
        for (int r = 0; r < TM; r++) s += (double)vA[r];
        g_partial[blockIdx.x] = s;   // deterministic
    }
}

// ---------------------------------------------------------------------------
// Kernel D: gather codebook rows by index and write (B, D, HWL) layout
// ---------------------------------------------------------------------------
__global__ __launch_bounds__(256)
void vq_scatter(const float* __restrict__ cb, float* __restrict__ outq) {
    __shared__ float qt[32*257];
    int b  = blockIdx.y;
    int s0 = blockIdx.x << 5;
    int t  = threadIdx.x;
    for (int i = t; i < 32*64; i += 256) {
        int r = i >> 6, c4 = i & 63;
        int k = g_idx[b*HWL + s0 + r];
        float4 v = *(const float4*)(cb + (size_t)k*EDIM + (c4 << 2));
        float* dst = qt + r*257 + (c4 << 2);
        dst[0] = v.x; dst[1] = v.y; dst[2] = v.z; dst[3] = v.w;
    }
    __syncthreads();
    int s = t & 31, dh = t >> 5;
    #pragma unroll
    for (int d = dh; d < EDIM; d += 8)
        outq[((size_t)b*EDIM + d)*HWL + s0 + s] = qt[s*257 + d];
}

// ---------------------------------------------------------------------------
// Kernel E: finalize loss = 1.25 * sum(min_dist) / (N*D)
// ---------------------------------------------------------------------------
__global__ void vq_finalize(float* out_loss) {
    double s = 0.0;
    for (int i = 0; i < NBLK; i++) s += g_partial[i];
    *out_loss = (float)(1.25 * s / (double)((size_t)NROWS*EDIM));
}

// ---------------------------------------------------------------------------
extern "C" void kernel_launch(void* const* d_in, const int* in_sizes, int n_in,
                              void* d_out, int out_size) {
    const float* z  = (const float*)d_in[0];
    const float* cb = (const float*)d_in[1];
    if (n_in >= 2 && in_sizes[0] == NEMB*EDIM && in_sizes[1] == NROWS*EDIM) {
        const float* tmp = z; z = cb; cb = tmp;   // defensive input-order check
    }
    float* out = (float*)d_out;

    const int QN = NROWS*EDIM;                    // 8388608
    bool has_quant = (out_size >= QN);
    bool full      = (out_size == QN + NROWS + 1);
    float* out_idx  = full ? out + QN         : nullptr;
    float* out_loss = full ? out + QN + NROWS : nullptr;

    const int smem_c = ((TM + TKC)*PITCH + TM + TKC + 2*TM + 2*TM) * 4;
    cudaFuncSetAttribute(vq_main, cudaFuncAttributeMaxDynamicSharedMemorySize, smem_c);

    vq_transpose<<<dim3(HWL/32, EDIM/32, BATCH), dim3(32, 8)>>>(z);
    vq_e2<<<(NEMB + 255)/256, 256>>>(cb);
    vq_main<<<NBLK, 256, smem_c>>>(cb, out_idx, full ? 1 : 0);
    if (has_quant)
        vq_scatter<<<dim3(HWL/32, BATCH), 256>>>(cb, out);
    if (full)
        vq_finalize<<<1, 1>>>(out_loss);
}